// round 7
// baseline (speedup 1.0000x reference)
#include <cuda_runtime.h>
#include <math.h>

#define NTA 512    // ab kernel threads
#define NTG 256    // gather kernel threads
#define RB  8      // rows (classes/codes) per ab block
#define GROWS 2048 // rows per gather row tile

struct Params {
  const int*   obs;
  const float *embed, *W1, *b1, *W2, *b2, *W3, *b3, *Wp, *bp, *codebook;
  const float *Wa, *ba, *Ws, *bs, *Wc1, *bc1, *Wc2, *bc2, *Wc3, *bc3, *Wc4, *bc4;
  float *out_actor, *out_scale, *out_critic, *out_loss, *out_idx;
  int NC, VQN, nClsBlk, B, nRowTiles;
};

// Device-global scratch (no allocation allowed)
__device__ int      g_idx_cls[1024];
__device__ float    g_loss_cls[1024];
__device__ float    g_tbl_actor[512 * 128];
__device__ float    g_tbl_scale[512 * 128];
__device__ float    g_tbl_crit[512];
__device__ float    g_partials[1024];
__device__ unsigned g_ticket;

struct SmemAB {
  float wbuf[2][16384];     // 128 KB double-buffered weights
  float A[RB][128];         // 4 KB
  float Bb[RB][128];        // 4 KB
  float part[3][RB][128];   // 12 KB k-quarter partials
  float dist[RB][512];      // 16 KB
  float znorm[RB];
};                          // ~164 KB

struct SmemG {
  float sT[512 * 32];       // 64 KB one-table 32-col slice
  short codes[GROWS];       // 4 KB
  float red[8];
  float s[NTG];
  int   lastblk;
};                          // ~69 KB -> 3 blocks/SM

__device__ __forceinline__ float sigf(float x) { return 1.0f / (1.0f + expf(-x)); }

// ---------------- cp.async helpers ----------------
__device__ __forceinline__ void cpa16(void* sdst, const void* gsrc) {
  unsigned s = (unsigned)__cvta_generic_to_shared(sdst);
  asm volatile("cp.async.cg.shared.global [%0], [%1], 16;\n" :: "r"(s), "l"(gsrc));
}
__device__ __forceinline__ void cpa_commit() { asm volatile("cp.async.commit_group;\n"); }
__device__ __forceinline__ void cpa_wait0()  { asm volatile("cp.async.wait_group 0;\n"); }

__device__ __forceinline__ void pf(float* dst, const float* src, int nfloats) {
  const int n4 = nfloats >> 2;
  for (int i = threadIdx.x; i < n4; i += NTA)
    cpa16(reinterpret_cast<float4*>(dst) + i, reinterpret_cast<const float4*>(src) + i);
  cpa_commit();
}

__device__ __forceinline__ float comp4(const float4& v, int j) {
  return j == 0 ? v.x : j == 1 ? v.y : j == 2 ? v.z : v.w;
}

// ---- RB(=8)-row GEMM layer, 2-row x k-quarter warp tiling (16 warps) ----
// warp w: rowgroup rg = w&3 (rows 2rg,2rg+1), kquarter kq = w>>2.
// lane = float4 column group (N/4 groups; lanes >= N/4 idle for N<128).
// ACT: 0 linear, 1 relu, 2 sigmoid, 3 sigmoid+1e-8
template<int K, int N, int ACT>
__device__ __forceinline__ void layerG(const float (*__restrict__ in)[128],
                                       const float* __restrict__ wb,
                                       const float* __restrict__ bias_g,
                                       float (*__restrict__ outs)[128],
                                       float* __restrict__ outg, int grow0,
                                       SmemAB& sm)
{
  const int tid = threadIdx.x, warp = tid >> 5, lane = tid & 31;
  const int rg = warp & 3, kq = warp >> 2;
  const int r0 = rg * 2;
  constexpr int NG = N / 4;
  const bool active = lane < NG;

  float4 acc[2];
  acc[0] = make_float4(0.f, 0.f, 0.f, 0.f);
  acc[1] = make_float4(0.f, 0.f, 0.f, 0.f);

  if (active) {
    const float4* w4 = reinterpret_cast<const float4*>(wb) + lane;
    const int kbeg = kq * (K / 4), kend = kbeg + (K / 4);
    #pragma unroll 2
    for (int k = kbeg; k < kend; k += 4) {
      float4 a[2];
      a[0] = *reinterpret_cast<const float4*>(&in[r0][k]);       // broadcast
      a[1] = *reinterpret_cast<const float4*>(&in[r0 + 1][k]);   // broadcast
      #pragma unroll
      for (int j = 0; j < 4; j++) {
        const float4 w = w4[(size_t)(k + j) * NG];
        #pragma unroll
        for (int r = 0; r < 2; r++) {
          const float aj = comp4(a[r], j);
          acc[r].x = fmaf(aj, w.x, acc[r].x);
          acc[r].y = fmaf(aj, w.y, acc[r].y);
          acc[r].z = fmaf(aj, w.z, acc[r].z);
          acc[r].w = fmaf(aj, w.w, acc[r].w);
        }
      }
    }
  }
  if (kq > 0 && active) {
    *reinterpret_cast<float4*>(&sm.part[kq - 1][r0][lane * 4])     = acc[0];
    *reinterpret_cast<float4*>(&sm.part[kq - 1][r0 + 1][lane * 4]) = acc[1];
  }
  __syncthreads();
  if (kq == 0 && active) {
    const float4 bb = __ldg(reinterpret_cast<const float4*>(bias_g) + lane);
    #pragma unroll
    for (int r = 0; r < 2; r++) {
      const float4 p1 = *reinterpret_cast<const float4*>(&sm.part[0][r0 + r][lane * 4]);
      const float4 p2 = *reinterpret_cast<const float4*>(&sm.part[1][r0 + r][lane * 4]);
      const float4 p3 = *reinterpret_cast<const float4*>(&sm.part[2][r0 + r][lane * 4]);
      float v[4] = {((acc[r].x + p1.x) + p2.x) + p3.x + bb.x,
                    ((acc[r].y + p1.y) + p2.y) + p3.y + bb.y,
                    ((acc[r].z + p1.z) + p2.z) + p3.z + bb.z,
                    ((acc[r].w + p1.w) + p2.w) + p3.w + bb.w};
      #pragma unroll
      for (int j = 0; j < 4; j++) {
        if (ACT == 1) v[j] = v[j] > 0.f ? v[j] : 0.f;
        if (ACT == 2 || ACT == 3) v[j] = sigf(v[j]);
        if (ACT == 3) v[j] += 1e-8f;
      }
      const float4 o = make_float4(v[0], v[1], v[2], v[3]);
      if (outs) *reinterpret_cast<float4*>(&outs[r0 + r][lane * 4]) = o;
      if (outg)
        reinterpret_cast<float4*>(outg)[(size_t)(grow0 + r0 + r) * NG + lane] = o;
    }
  }
  __syncthreads();
}

__global__ void __launch_bounds__(NTA, 1) acsq_ab(Params p)
{
  extern __shared__ char smraw[];
  SmemAB& sm = *reinterpret_cast<SmemAB*>(smraw);
  const int tid = threadIdx.x;

  if ((int)blockIdx.x < p.nClsBlk) {
    // ================= CLASS PATH: 8 classes =================
    const int c0 = blockIdx.x * RB;

    pf(sm.wbuf[0], p.W1, 128 * 128);
    if (tid < RB * 32) {   // embed gather: 8 rows x 32 float4
      const int r = tid >> 5, col = tid & 31, cls = c0 + r;
      float4 v = make_float4(0.f, 0.f, 0.f, 0.f);
      if (cls < p.NC)
        v = __ldg(reinterpret_cast<const float4*>(p.embed + (size_t)cls * 128) + col);
      reinterpret_cast<float4*>(sm.A[r])[col] = v;
    }
    cpa_wait0(); __syncthreads();

    pf(sm.wbuf[1], p.W2, 128 * 128);
    layerG<128, 128, 1>(sm.A, sm.wbuf[0], p.b1, sm.Bb, nullptr, 0, sm);
    cpa_wait0(); __syncthreads();

    pf(sm.wbuf[0], p.W3, 128 * 128);
    layerG<128, 128, 1>(sm.Bb, sm.wbuf[1], p.b2, sm.A, nullptr, 0, sm);
    cpa_wait0(); __syncthreads();

    pf(sm.wbuf[1], p.Wp, 128 * 64);
    layerG<128, 128, 1>(sm.A, sm.wbuf[0], p.b3, sm.Bb, nullptr, 0, sm);
    cpa_wait0(); __syncthreads();

    layerG<128, 64, 0>(sm.Bb, sm.wbuf[1], p.bp, sm.A, nullptr, 0, sm);
    // z in A[:,0:64]
    if (tid < RB) {
      float s = 0.f;
      #pragma unroll
      for (int k = 0; k < 64; k++) s = fmaf(sm.A[tid][k], sm.A[tid][k], s);
      sm.znorm[tid] = s;
    }
    __syncthreads();

    // ---- VQ distances: one thread per code ----
    {
      const int cc = tid;
      if (cc < p.VQN) {
        float4 cb[16];
        const float4* cp = reinterpret_cast<const float4*>(p.codebook + (size_t)cc * 64);
        #pragma unroll
        for (int q = 0; q < 16; q++) cb[q] = __ldg(cp + q);
        float cn = 0.f;
        #pragma unroll
        for (int q = 0; q < 16; q++) {
          cn = fmaf(cb[q].x, cb[q].x, cn); cn = fmaf(cb[q].y, cb[q].y, cn);
          cn = fmaf(cb[q].z, cb[q].z, cn); cn = fmaf(cb[q].w, cb[q].w, cn);
        }
        #pragma unroll
        for (int r = 0; r < RB; r++) {
          const float4* A4 = reinterpret_cast<const float4*>(sm.A[r]);
          float dot = 0.f;
          #pragma unroll
          for (int q = 0; q < 16; q++) {
            const float4 a = A4[q];               // broadcast LDS.128
            dot = fmaf(a.x, cb[q].x, dot); dot = fmaf(a.y, cb[q].y, dot);
            dot = fmaf(a.z, cb[q].z, dot); dot = fmaf(a.w, cb[q].w, dot);
          }
          sm.dist[r][cc] = sm.znorm[r] - 2.f * dot + cn;
        }
      }
    }
    __syncthreads();

    // ---- argmin per row (warps 0..7), lexicographic (d, idx) ----
    const int warp = tid >> 5, lane = tid & 31;
    if (warp < RB) {
      const int r = warp;
      float best = 3.4e38f; int bi = 0;
      for (int cc = lane; cc < p.VQN; cc += 32) {
        const float d = sm.dist[r][cc];
        if (d < best) { best = d; bi = cc; }
      }
      #pragma unroll
      for (int o = 16; o; o >>= 1) {
        const float ob = __shfl_down_sync(0xffffffffu, best, o);
        const int   oi = __shfl_down_sync(0xffffffffu, bi,   o);
        if (ob < best || (ob == best && oi < bi)) { best = ob; bi = oi; }
      }
      bi = __shfl_sync(0xffffffffu, bi, 0);
      float ls = 0.f;
      for (int k = lane; k < 64; k += 32) {
        const float dq = __ldg(p.codebook + (size_t)bi * 64 + k) - sm.A[r][k];
        ls = fmaf(dq, dq, ls);
      }
      #pragma unroll
      for (int o = 16; o; o >>= 1) ls += __shfl_down_sync(0xffffffffu, ls, o);
      if (lane == 0 && c0 + r < p.NC) {
        g_idx_cls[c0 + r]  = bi;
        g_loss_cls[c0 + r] = ls;
      }
    }
  } else {
    // ================= HEAD PATH: 8 codes =================
    const int q0 = (blockIdx.x - p.nClsBlk) * RB;

    pf(sm.wbuf[0], p.Wa, 64 * 128);
    if (tid < RB * 16) {     // gather 8 codebook rows
      const int r = tid >> 4, col = tid & 15;
      reinterpret_cast<float4*>(sm.A[r])[col] =
          __ldg(reinterpret_cast<const float4*>(p.codebook + (size_t)(q0 + r) * 64) + col);
    }
    cpa_wait0(); __syncthreads();

    pf(sm.wbuf[1], p.Ws, 64 * 128);
    layerG<64, 128, 2>(sm.A, sm.wbuf[0], p.ba, nullptr, g_tbl_actor, q0, sm);
    cpa_wait0(); __syncthreads();

    pf(sm.wbuf[0], p.Wc1, 64 * 128);
    layerG<64, 128, 3>(sm.A, sm.wbuf[1], p.bs, nullptr, g_tbl_scale, q0, sm);
    cpa_wait0(); __syncthreads();

    pf(sm.wbuf[1], p.Wc2, 128 * 128);
    layerG<64, 128, 2>(sm.A, sm.wbuf[0], p.bc1, sm.Bb, nullptr, 0, sm);
    cpa_wait0(); __syncthreads();

    pf(sm.wbuf[0], p.Wc3, 128 * 32);
    layerG<128, 128, 2>(sm.Bb, sm.wbuf[1], p.bc2, sm.A, nullptr, 0, sm);
    cpa_wait0(); __syncthreads();

    layerG<128, 32, 2>(sm.A, sm.wbuf[0], p.bc3, sm.Bb, nullptr, 0, sm);

    if (tid < RB) {
      float s = __ldg(p.bc4);
      #pragma unroll
      for (int k = 0; k < 32; k++) s = fmaf(sm.Bb[tid][k], __ldg(p.Wc4 + k), s);
      g_tbl_crit[q0 + tid] = s;
    }
  }
}

// ==== gather v3: grid = nRowTiles x (4 colgroups x 2 tables), 64KB slice ====
__global__ void __launch_bounds__(NTG) acsq_gather(Params p, float scale)
{
  extern __shared__ char smraw[];
  SmemG& sm = *reinterpret_cast<SmemG*>(smraw);
  const int tid = threadIdx.x;
  const int sub = blockIdx.x & 7;                // 0..7
  const int tbl = sub & 1;                       // 0=actor 1=scale
  const int cg  = sub >> 1;                      // column group (32 cols)
  const int rt  = blockIdx.x >> 3;               // row tile
  const size_t row0 = (size_t)rt * GROWS;
  const int c0 = cg * 32;

  if (tid == 0) sm.lastblk = 0;

  // stage 32-column slice of one table (cp.async, 64 KB)
  {
    const float* src = tbl ? g_tbl_scale : g_tbl_actor;
    for (int i = tid; i < 512 * 8; i += NTG) {
      const int row = i >> 3, q = i & 7;
      cpa16(&sm.sT[row * 32 + q * 4], &src[row * 128 + c0 + q * 4]);
    }
  }
  cpa_commit();

  // codes for this tile (+ idx/critic/loss on sub==0) while cp.async flies
  float lp = 0.f;
  for (int i = tid; i < GROWS; i += NTG) {
    const size_t b = row0 + i;
    short code = 0;
    if (b < (size_t)p.B) {
      const int o = p.obs[b];
      const int cd = g_idx_cls[o];
      code = (short)cd;
      if (sub == 0) {
        p.out_idx[b]    = (float)cd;
        p.out_critic[b] = g_tbl_crit[cd];
        lp += g_loss_cls[o];
      }
    }
    sm.codes[i] = code;
  }
  if (sub == 0) {
    #pragma unroll
    for (int o = 16; o; o >>= 1) lp += __shfl_down_sync(0xffffffffu, lp, o);
    if ((tid & 31) == 0) sm.red[tid >> 5] = lp;
  }
  __syncthreads();
  if (sub == 0 && tid == 0) {
    float t = 0.f;
    #pragma unroll
    for (int w = 0; w < 8; w++) t += sm.red[w];
    g_partials[rt] = t;
    __threadfence();
    sm.lastblk = (atomicAdd(&g_ticket, 1u) == (unsigned)(p.nRowTiles - 1)) ? 1 : 0;
  }
  cpa_wait0();
  __syncthreads();

  // main copy: smem slice -> global (LTS sees only the writes)
  {
    const float4* sT4 = reinterpret_cast<const float4*>(sm.sT);
    float4* od = reinterpret_cast<float4*>(tbl ? p.out_scale : p.out_actor);
    #pragma unroll 4
    for (int i = tid; i < GROWS * 8; i += NTG) {
      const int r = i >> 3, q = i & 7;
      const size_t b = row0 + r;
      if (b < (size_t)p.B) {
        const int cd = sm.codes[r];
        od[b * 32 + cg * 8 + q] = sT4[cd * 8 + q];
      }
    }
  }

  if (sm.lastblk) {
    float v = 0.f;
    for (int i = tid; i < p.nRowTiles; i += NTG) v += g_partials[i];  // fixed order
    sm.s[tid] = v;
    __syncthreads();
    for (int o = NTG / 2; o > 0; o >>= 1) {
      if (tid < o) sm.s[tid] += sm.s[tid + o];
      __syncthreads();
    }
    if (tid == 0) { *p.out_loss = sm.s[0] * scale; g_ticket = 0u; }
  }
}

extern "C" void kernel_launch(void* const* d_in, const int* in_sizes, int n_in,
                              void* d_out, int out_size)
{
  Params p;
  p.obs      = (const int*)d_in[0];
  p.embed    = (const float*)d_in[1];
  p.W1  = (const float*)d_in[2];  p.b1  = (const float*)d_in[3];
  p.W2  = (const float*)d_in[4];  p.b2  = (const float*)d_in[5];
  p.W3  = (const float*)d_in[6];  p.b3  = (const float*)d_in[7];
  p.Wp  = (const float*)d_in[8];  p.bp  = (const float*)d_in[9];
  p.codebook = (const float*)d_in[10];
  p.Wa  = (const float*)d_in[11]; p.ba  = (const float*)d_in[12];
  p.Ws  = (const float*)d_in[13]; p.bs  = (const float*)d_in[14];
  p.Wc1 = (const float*)d_in[15]; p.bc1 = (const float*)d_in[16];
  p.Wc2 = (const float*)d_in[17]; p.bc2 = (const float*)d_in[18];
  p.Wc3 = (const float*)d_in[19]; p.bc3 = (const float*)d_in[20];
  p.Wc4 = (const float*)d_in[21]; p.bc4 = (const float*)d_in[22];

  const int B   = in_sizes[0];
  const int NC  = in_sizes[1] / 128;   // embed is [NC, 128]
  const int VQN = in_sizes[10] / 64;   // codebook is [VQN, 64]
  p.B = B; p.NC = NC; p.VQN = VQN;
  p.nClsBlk   = (NC + RB - 1) / RB;
  p.nRowTiles = (B + GROWS - 1) / GROWS;

  float* out = (float*)d_out;
  p.out_actor  = out;                                  // [B,128]
  p.out_scale  = out + (size_t)B * 128;                // [B,128]
  p.out_critic = out + (size_t)2 * B * 128;            // [B]
  p.out_loss   = out + (size_t)2 * B * 128 + B;        // scalar
  p.out_idx    = out + (size_t)2 * B * 128 + B + 1;    // [B] as float

  const int headBlk = (VQN + RB - 1) / RB;
  cudaFuncSetAttribute(acsq_ab, cudaFuncAttributeMaxDynamicSharedMemorySize,
                       (int)sizeof(SmemAB));
  cudaFuncSetAttribute(acsq_gather, cudaFuncAttributeMaxDynamicSharedMemorySize,
                       (int)sizeof(SmemG));
  acsq_ab<<<p.nClsBlk + headBlk, NTA, sizeof(SmemAB)>>>(p);
  acsq_gather<<<p.nRowTiles * 8, NTG, sizeof(SmemG)>>>(p, 1.25f / ((float)B * 64.f));
}

// round 8
// speedup vs baseline: 1.2298x; 1.2298x over previous
#include <cuda_runtime.h>
#include <math.h>

#define NTA 512    // ab kernel threads
#define NTG 256    // gather kernel threads
#define RB  16     // rows (classes/codes) per ab block

struct Params {
  const int*   obs;
  const float *embed, *W1, *b1, *W2, *b2, *W3, *b3, *Wp, *bp, *codebook;
  const float *Wa, *ba, *Ws, *bs, *Wc1, *bc1, *Wc2, *bc2, *Wc3, *bc3, *Wc4, *bc4;
  float *out_actor, *out_scale, *out_critic, *out_loss, *out_idx;
  int NC, VQN, nClsBlk, B, gblocks;
};

// Device-global scratch (no allocation allowed)
__device__ int      g_idx_cls[1024];
__device__ float    g_loss_cls[1024];
__device__ float    g_tbl_actor[512 * 128];
__device__ float    g_tbl_scale[512 * 128];
__device__ float    g_tbl_crit[512];
__device__ float    g_partials[1024];
__device__ unsigned g_ticket;

struct SmemAB {
  float wbuf[2][16384];     // 128 KB double-buffered weights
  float A[RB][128];         // 8 KB
  float Bb[RB][128];        // 8 KB
  float part[3][RB][128];   // 24 KB k-quarter partials
  float dist[RB][512];      // 32 KB
  float znorm[RB];
};                          // ~200 KB

__device__ __forceinline__ float sigf(float x) { return 1.0f / (1.0f + expf(-x)); }

// ---------------- cp.async helpers ----------------
__device__ __forceinline__ void cpa16(void* sdst, const void* gsrc) {
  unsigned s = (unsigned)__cvta_generic_to_shared(sdst);
  asm volatile("cp.async.cg.shared.global [%0], [%1], 16;\n" :: "r"(s), "l"(gsrc));
}
__device__ __forceinline__ void cpa_commit() { asm volatile("cp.async.commit_group;\n"); }
__device__ __forceinline__ void cpa_wait0()  { asm volatile("cp.async.wait_group 0;\n"); }

__device__ __forceinline__ void pf(float* dst, const float* src, int nfloats) {
  const int n4 = nfloats >> 2;
  for (int i = threadIdx.x; i < n4; i += NTA)
    cpa16(reinterpret_cast<float4*>(dst) + i, reinterpret_cast<const float4*>(src) + i);
  cpa_commit();
}

__device__ __forceinline__ float comp4(const float4& v, int j) {
  return j == 0 ? v.x : j == 1 ? v.y : j == 2 ? v.z : v.w;
}

// ---- 16-row GEMM layer, (kq, colquarter) warp x (slot, rowgroup) lane ----
// warp w (16): kq = w>>2 (k-quarter), cq = w&3 (column quarter of N/4 cols).
// lane: slot = lane&7 (float4 col within quarter), rg = lane>>3 (rows 4rg..4rg+3).
// Each weight LDS.128 hits 8 distinct addrs (4-way broadcast) -> 1 phase,
// and each weight element is read by exactly ONE warp.
// ACT: 0 linear, 1 relu, 2 sigmoid, 3 sigmoid+1e-8
template<int K, int N, int ACT>
__device__ __forceinline__ void layerW(const float (*__restrict__ in)[128],
                                       const float* __restrict__ wb,
                                       const float* __restrict__ bias_g,
                                       float (*__restrict__ outs)[128],
                                       float* __restrict__ outg, int grow0,
                                       SmemAB& sm)
{
  const int tid = threadIdx.x, warp = tid >> 5, lane = tid & 31;
  const int kq = warp >> 2, cq = warp & 3;
  constexpr int NG  = N / 4;      // float4 per output row
  constexpr int SPC = NG / 4;     // float4 slots per column-quarter
  const int slot = lane & 7, rg = lane >> 3;
  const int c4 = cq * SPC + slot; // this lane's float4 column
  const int r0 = rg * 4;          // this lane's 4 rows
  const bool active = slot < SPC;

  float4 acc[4];
  #pragma unroll
  for (int r = 0; r < 4; r++) acc[r] = make_float4(0.f, 0.f, 0.f, 0.f);

  if (active) {
    const float4* w4 = reinterpret_cast<const float4*>(wb) + c4;
    const int kbeg = kq * (K / 4), kend = kbeg + (K / 4);
    #pragma unroll 2
    for (int k = kbeg; k < kend; k += 4) {
      float4 a[4];
      #pragma unroll
      for (int r = 0; r < 4; r++)
        a[r] = *reinterpret_cast<const float4*>(&in[r0 + r][k]);  // 4 addrs/warp
      #pragma unroll
      for (int j = 0; j < 4; j++) {
        const float4 w = w4[(size_t)(k + j) * NG];                // 8 addrs/warp
        #pragma unroll
        for (int r = 0; r < 4; r++) {
          const float aj = comp4(a[r], j);
          acc[r].x = fmaf(aj, w.x, acc[r].x);
          acc[r].y = fmaf(aj, w.y, acc[r].y);
          acc[r].z = fmaf(aj, w.z, acc[r].z);
          acc[r].w = fmaf(aj, w.w, acc[r].w);
        }
      }
    }
  }
  if (kq > 0 && active) {
    #pragma unroll
    for (int r = 0; r < 4; r++)
      *reinterpret_cast<float4*>(&sm.part[kq - 1][r0 + r][c4 * 4]) = acc[r];
  }
  __syncthreads();
  if (kq == 0 && active) {
    const float4 bb = __ldg(reinterpret_cast<const float4*>(bias_g) + c4);
    #pragma unroll
    for (int r = 0; r < 4; r++) {
      const float4 p1 = *reinterpret_cast<const float4*>(&sm.part[0][r0 + r][c4 * 4]);
      const float4 p2 = *reinterpret_cast<const float4*>(&sm.part[1][r0 + r][c4 * 4]);
      const float4 p3 = *reinterpret_cast<const float4*>(&sm.part[2][r0 + r][c4 * 4]);
      float v[4] = {((acc[r].x + p1.x) + p2.x) + p3.x + bb.x,
                    ((acc[r].y + p1.y) + p2.y) + p3.y + bb.y,
                    ((acc[r].z + p1.z) + p2.z) + p3.z + bb.z,
                    ((acc[r].w + p1.w) + p2.w) + p3.w + bb.w};
      #pragma unroll
      for (int j = 0; j < 4; j++) {
        if (ACT == 1) v[j] = v[j] > 0.f ? v[j] : 0.f;
        if (ACT == 2 || ACT == 3) v[j] = sigf(v[j]);
        if (ACT == 3) v[j] += 1e-8f;
      }
      const float4 o = make_float4(v[0], v[1], v[2], v[3]);
      if (outs) *reinterpret_cast<float4*>(&outs[r0 + r][c4 * 4]) = o;
      if (outg)
        reinterpret_cast<float4*>(outg)[(size_t)(grow0 + r0 + r) * NG + c4] = o;
    }
  }
  __syncthreads();
}

__global__ void __launch_bounds__(NTA, 1) acsq_ab(Params p)
{
  extern __shared__ char smraw[];
  SmemAB& sm = *reinterpret_cast<SmemAB*>(smraw);
  const int tid = threadIdx.x;

  if ((int)blockIdx.x < p.nClsBlk) {
    // ================= CLASS PATH: 16 classes =================
    const int c0 = blockIdx.x * RB;

    pf(sm.wbuf[0], p.W1, 128 * 128);
    {   // embed gather: 16 rows x 32 float4
      const int r = tid >> 5, col = tid & 31, cls = c0 + r;
      float4 v = make_float4(0.f, 0.f, 0.f, 0.f);
      if (cls < p.NC)
        v = __ldg(reinterpret_cast<const float4*>(p.embed + (size_t)cls * 128) + col);
      reinterpret_cast<float4*>(sm.A[r])[col] = v;
    }
    cpa_wait0(); __syncthreads();

    pf(sm.wbuf[1], p.W2, 128 * 128);
    layerW<128, 128, 1>(sm.A, sm.wbuf[0], p.b1, sm.Bb, nullptr, 0, sm);
    cpa_wait0(); __syncthreads();

    pf(sm.wbuf[0], p.W3, 128 * 128);
    layerW<128, 128, 1>(sm.Bb, sm.wbuf[1], p.b2, sm.A, nullptr, 0, sm);
    cpa_wait0(); __syncthreads();

    pf(sm.wbuf[1], p.Wp, 128 * 64);
    layerW<128, 128, 1>(sm.A, sm.wbuf[0], p.b3, sm.Bb, nullptr, 0, sm);
    cpa_wait0(); __syncthreads();

    layerW<128, 64, 0>(sm.Bb, sm.wbuf[1], p.bp, sm.A, nullptr, 0, sm);
    // z in A[:,0:64]
    if (tid < RB) {
      float s = 0.f;
      #pragma unroll
      for (int k = 0; k < 64; k++) s = fmaf(sm.A[tid][k], sm.A[tid][k], s);
      sm.znorm[tid] = s;
    }
    __syncthreads();

    // ---- VQ distances: one thread per code ----
    {
      const int cc = tid;
      if (cc < p.VQN) {
        float4 cb[16];
        const float4* cp = reinterpret_cast<const float4*>(p.codebook + (size_t)cc * 64);
        #pragma unroll
        for (int q = 0; q < 16; q++) cb[q] = __ldg(cp + q);
        float cn = 0.f;
        #pragma unroll
        for (int q = 0; q < 16; q++) {
          cn = fmaf(cb[q].x, cb[q].x, cn); cn = fmaf(cb[q].y, cb[q].y, cn);
          cn = fmaf(cb[q].z, cb[q].z, cn); cn = fmaf(cb[q].w, cb[q].w, cn);
        }
        #pragma unroll
        for (int r = 0; r < RB; r++) {
          const float4* A4 = reinterpret_cast<const float4*>(sm.A[r]);
          float dot = 0.f;
          #pragma unroll
          for (int q = 0; q < 16; q++) {
            const float4 a = A4[q];               // broadcast LDS.128
            dot = fmaf(a.x, cb[q].x, dot); dot = fmaf(a.y, cb[q].y, dot);
            dot = fmaf(a.z, cb[q].z, dot); dot = fmaf(a.w, cb[q].w, dot);
          }
          sm.dist[r][cc] = sm.znorm[r] - 2.f * dot + cn;
        }
      }
    }
    __syncthreads();

    // ---- argmin per row (warp r of 16), lexicographic (d, idx) ----
    const int warp = tid >> 5, lane = tid & 31;
    {
      const int r = warp;
      float best = 3.4e38f; int bi = 0;
      for (int cc = lane; cc < p.VQN; cc += 32) {
        const float d = sm.dist[r][cc];
        if (d < best) { best = d; bi = cc; }
      }
      #pragma unroll
      for (int o = 16; o; o >>= 1) {
        const float ob = __shfl_down_sync(0xffffffffu, best, o);
        const int   oi = __shfl_down_sync(0xffffffffu, bi,   o);
        if (ob < best || (ob == best && oi < bi)) { best = ob; bi = oi; }
      }
      bi = __shfl_sync(0xffffffffu, bi, 0);
      float ls = 0.f;
      for (int k = lane; k < 64; k += 32) {
        const float dq = __ldg(p.codebook + (size_t)bi * 64 + k) - sm.A[r][k];
        ls = fmaf(dq, dq, ls);
      }
      #pragma unroll
      for (int o = 16; o; o >>= 1) ls += __shfl_down_sync(0xffffffffu, ls, o);
      if (lane == 0 && c0 + r < p.NC) {
        g_idx_cls[c0 + r]  = bi;
        g_loss_cls[c0 + r] = ls;
      }
    }
  } else {
    // ================= HEAD PATH: 16 codes =================
    const int q0 = (blockIdx.x - p.nClsBlk) * RB;

    pf(sm.wbuf[0], p.Wa, 64 * 128);
    if (tid < RB * 16) {     // gather 16 codebook rows
      const int r = tid >> 4, col = tid & 15;
      reinterpret_cast<float4*>(sm.A[r])[col] =
          __ldg(reinterpret_cast<const float4*>(p.codebook + (size_t)(q0 + r) * 64) + col);
    }
    cpa_wait0(); __syncthreads();

    pf(sm.wbuf[1], p.Ws, 64 * 128);
    layerW<64, 128, 2>(sm.A, sm.wbuf[0], p.ba, nullptr, g_tbl_actor, q0, sm);
    cpa_wait0(); __syncthreads();

    pf(sm.wbuf[0], p.Wc1, 64 * 128);
    layerW<64, 128, 3>(sm.A, sm.wbuf[1], p.bs, nullptr, g_tbl_scale, q0, sm);
    cpa_wait0(); __syncthreads();

    pf(sm.wbuf[1], p.Wc2, 128 * 128);
    layerW<64, 128, 2>(sm.A, sm.wbuf[0], p.bc1, sm.Bb, nullptr, 0, sm);
    cpa_wait0(); __syncthreads();

    pf(sm.wbuf[0], p.Wc3, 128 * 32);
    layerW<128, 128, 2>(sm.Bb, sm.wbuf[1], p.bc2, sm.A, nullptr, 0, sm);
    cpa_wait0(); __syncthreads();

    layerW<128, 32, 2>(sm.A, sm.wbuf[0], p.bc3, sm.Bb, nullptr, 0, sm);

    if (tid < RB) {
      float s = __ldg(p.bc4);
      #pragma unroll
      for (int k = 0; k < 32; k++) s = fmaf(sm.Bb[tid][k], __ldg(p.Wc4 + k), s);
      g_tbl_crit[q0 + tid] = s;
    }
  }
}

// ======= gather (R4 version, proven 26 us) + fused final loss reduce =======
__global__ void __launch_bounds__(NTG) acsq_gather(Params p, float scale)
{
  __shared__ int   codes[NTG];
  __shared__ float red[8];
  __shared__ float s[NTG];
  __shared__ bool  lastblk;
  const int tid = threadIdx.x;
  const size_t row0 = (size_t)blockIdx.x * NTG;
  const size_t b = row0 + tid;

  float lp = 0.f;
  int code = 0;
  if (b < (size_t)p.B) {
    const int o = p.obs[b];
    code = g_idx_cls[o];
    lp = g_loss_cls[o];
    p.out_idx[b]    = (float)code;
    p.out_critic[b] = g_tbl_crit[code];
  }
  codes[tid] = code;

  #pragma unroll
  for (int o = 16; o; o >>= 1) lp += __shfl_down_sync(0xffffffffu, lp, o);
  if ((tid & 31) == 0) red[tid >> 5] = lp;
  __syncthreads();
  if (tid == 0) {
    float t = 0.f;
    #pragma unroll
    for (int w = 0; w < 8; w++) t += red[w];
    g_partials[blockIdx.x] = t;
    __threadfence();
    lastblk = (atomicAdd(&g_ticket, 1u) == (unsigned)(gridDim.x - 1));
  }

  const float4* ta = reinterpret_cast<const float4*>(g_tbl_actor);
  const float4* ts = reinterpret_cast<const float4*>(g_tbl_scale);
  float4* oa = reinterpret_cast<float4*>(p.out_actor);
  float4* os = reinterpret_cast<float4*>(p.out_scale);
  __syncthreads();
  for (int i = tid; i < NTG * 32; i += NTG) {
    const int r = i >> 5, cc = i & 31;
    if (row0 + r < (size_t)p.B) {
      const int cd = codes[r];
      oa[(row0 + r) * 32 + cc] = ta[cd * 32 + cc];
      os[(row0 + r) * 32 + cc] = ts[cd * 32 + cc];
    }
  }

  if (lastblk) {
    float v = 0.f;
    for (int i = tid; i < p.gblocks; i += NTG) v += g_partials[i];  // fixed order
    s[tid] = v;
    __syncthreads();
    for (int o = NTG / 2; o > 0; o >>= 1) {
      if (tid < o) s[tid] += s[tid + o];
      __syncthreads();
    }
    if (tid == 0) { *p.out_loss = s[0] * scale; g_ticket = 0u; }
  }
}

extern "C" void kernel_launch(void* const* d_in, const int* in_sizes, int n_in,
                              void* d_out, int out_size)
{
  Params p;
  p.obs      = (const int*)d_in[0];
  p.embed    = (const float*)d_in[1];
  p.W1  = (const float*)d_in[2];  p.b1  = (const float*)d_in[3];
  p.W2  = (const float*)d_in[4];  p.b2  = (const float*)d_in[5];
  p.W3  = (const float*)d_in[6];  p.b3  = (const float*)d_in[7];
  p.Wp  = (const float*)d_in[8];  p.bp  = (const float*)d_in[9];
  p.codebook = (const float*)d_in[10];
  p.Wa  = (const float*)d_in[11]; p.ba  = (const float*)d_in[12];
  p.Ws  = (const float*)d_in[13]; p.bs  = (const float*)d_in[14];
  p.Wc1 = (const float*)d_in[15]; p.bc1 = (const float*)d_in[16];
  p.Wc2 = (const float*)d_in[17]; p.bc2 = (const float*)d_in[18];
  p.Wc3 = (const float*)d_in[19]; p.bc3 = (const float*)d_in[20];
  p.Wc4 = (const float*)d_in[21]; p.bc4 = (const float*)d_in[22];

  const int B   = in_sizes[0];
  const int NC  = in_sizes[1] / 128;   // embed is [NC, 128]
  const int VQN = in_sizes[10] / 64;   // codebook is [VQN, 64]
  p.B = B; p.NC = NC; p.VQN = VQN;
  p.nClsBlk = (NC + RB - 1) / RB;
  p.gblocks = (B + NTG - 1) / NTG;

  float* out = (float*)d_out;
  p.out_actor  = out;                                  // [B,128]
  p.out_scale  = out + (size_t)B * 128;                // [B,128]
  p.out_critic = out + (size_t)2 * B * 128;            // [B]
  p.out_loss   = out + (size_t)2 * B * 128 + B;        // scalar
  p.out_idx    = out + (size_t)2 * B * 128 + B + 1;    // [B] as float

  const int headBlk = (VQN + RB - 1) / RB;
  cudaFuncSetAttribute(acsq_ab, cudaFuncAttributeMaxDynamicSharedMemorySize,
                       (int)sizeof(SmemAB));
  acsq_ab<<<p.nClsBlk + headBlk, NTA, sizeof(SmemAB)>>>(p);
  acsq_gather<<<p.gblocks, NTG>>>(p, 1.25f / ((float)B * 64.f));
}

// round 9
// speedup vs baseline: 1.2504x; 1.0167x over previous
#include <cuda_runtime.h>
#include <math.h>

#define NTA 512    // ab kernel threads
#define NTG 256    // gather kernel threads
#define RB  16     // rows (classes/codes) per ab block

struct Params {
  const int*   obs;
  const float *embed, *W1, *b1, *W2, *b2, *W3, *b3, *Wp, *bp, *codebook;
  const float *Wa, *ba, *Ws, *bs, *Wc1, *bc1, *Wc2, *bc2, *Wc3, *bc3, *Wc4, *bc4;
  float *out_actor, *out_scale, *out_critic, *out_loss, *out_idx;
  int NC, VQN, nClsBlk, B, gblocks;
};

// Device-global scratch (no allocation allowed)
__device__ int      g_idx_cls[1024];
__device__ float    g_loss_cls[1024];
__device__ float    g_tbl_actor[512 * 128];
__device__ float    g_tbl_scale[512 * 128];
__device__ float    g_tbl_crit[512];
__device__ float    g_partials[1024];
__device__ unsigned g_ticket;

struct SmemAB {
  float wbuf[2][16384];     // 128 KB double-buffered weights
  float A[RB][128];         // 8 KB
  float Bb[RB][128];        // 8 KB
  float part[3][RB][128];   // 24 KB k-quarter partials
  float dist[RB][512];      // 32 KB
  float znorm[RB];
};                          // ~200 KB

__device__ __forceinline__ float sigf(float x) { return 1.0f / (1.0f + expf(-x)); }

// ---------------- packed f32x2 helpers ----------------
__device__ __forceinline__ unsigned long long pack_dup(float a) {
  unsigned long long d;
  const unsigned ai = __float_as_uint(a);
  asm("mov.b64 %0, {%1, %1};" : "=l"(d) : "r"(ai));
  return d;
}
__device__ __forceinline__ void fma2(unsigned long long& d, unsigned long long a,
                                     unsigned long long b) {
  asm("fma.rn.f32x2 %0, %1, %2, %0;" : "+l"(d) : "l"(a), "l"(b));
}
__device__ __forceinline__ float lo32(unsigned long long v) {
  return __uint_as_float((unsigned)(v & 0xffffffffull));
}
__device__ __forceinline__ float hi32(unsigned long long v) {
  return __uint_as_float((unsigned)(v >> 32));
}

// ---------------- cp.async helpers ----------------
__device__ __forceinline__ void cpa16(void* sdst, const void* gsrc) {
  unsigned s = (unsigned)__cvta_generic_to_shared(sdst);
  asm volatile("cp.async.cg.shared.global [%0], [%1], 16;\n" :: "r"(s), "l"(gsrc));
}
__device__ __forceinline__ void cpa_commit() { asm volatile("cp.async.commit_group;\n"); }
__device__ __forceinline__ void cpa_wait0()  { asm volatile("cp.async.wait_group 0;\n"); }

__device__ __forceinline__ void pf(float* dst, const float* src, int nfloats) {
  const int n4 = nfloats >> 2;
  for (int i = threadIdx.x; i < n4; i += NTA)
    cpa16(reinterpret_cast<float4*>(dst) + i, reinterpret_cast<const float4*>(src) + i);
  cpa_commit();
}

__device__ __forceinline__ float comp4(const float4& v, int j) {
  return j == 0 ? v.x : j == 1 ? v.y : j == 2 ? v.z : v.w;
}

// ---- 16-row GEMM layer, (kq, colquarter) warp x (slot, rowgroup) lane ----
// FFMA2 paired across COLUMNS: each column's k-sum order unchanged (bit-exact
// vs scalar version). a-dup packs ride the ALU pipe.
// ACT: 0 linear, 1 relu, 2 sigmoid, 3 sigmoid+1e-8
template<int K, int N, int ACT>
__device__ __forceinline__ void layerW(const float (*__restrict__ in)[128],
                                       const float* __restrict__ wb,
                                       const float* __restrict__ bias_g,
                                       float (*__restrict__ outs)[128],
                                       float* __restrict__ outg, int grow0,
                                       SmemAB& sm)
{
  const int tid = threadIdx.x, warp = tid >> 5, lane = tid & 31;
  const int kq = warp >> 2, cq = warp & 3;
  constexpr int NG  = N / 4;      // float4 per output row
  constexpr int SPC = NG / 4;     // float4 slots per column-quarter
  const int slot = lane & 7, rg = lane >> 3;
  const int c4 = cq * SPC + slot; // this lane's float4 column
  const int r0 = rg * 4;          // this lane's 4 rows
  const bool active = slot < SPC;

  unsigned long long acc01[4], acc23[4];   // per row: col pairs (c0,c1),(c2,c3)
  #pragma unroll
  for (int r = 0; r < 4; r++) { acc01[r] = 0ull; acc23[r] = 0ull; }

  if (active) {
    const ulonglong2* w2 = reinterpret_cast<const ulonglong2*>(wb) + c4;
    const int kbeg = kq * (K / 4), kend = kbeg + (K / 4);
    #pragma unroll 2
    for (int k = kbeg; k < kend; k += 4) {
      float4 a[4];
      #pragma unroll
      for (int r = 0; r < 4; r++)
        a[r] = *reinterpret_cast<const float4*>(&in[r0 + r][k]);
      #pragma unroll
      for (int j = 0; j < 4; j++) {
        const ulonglong2 w = w2[(size_t)(k + j) * NG];
        #pragma unroll
        for (int r = 0; r < 4; r++) {
          const unsigned long long aa = pack_dup(comp4(a[r], j));
          fma2(acc01[r], aa, w.x);
          fma2(acc23[r], aa, w.y);
        }
      }
    }
  }
  if (kq > 0 && active) {
    #pragma unroll
    for (int r = 0; r < 4; r++) {
      const float4 o = make_float4(lo32(acc01[r]), hi32(acc01[r]),
                                   lo32(acc23[r]), hi32(acc23[r]));
      *reinterpret_cast<float4*>(&sm.part[kq - 1][r0 + r][c4 * 4]) = o;
    }
  }
  __syncthreads();
  if (kq == 0 && active) {
    const float4 bb = __ldg(reinterpret_cast<const float4*>(bias_g) + c4);
    #pragma unroll
    for (int r = 0; r < 4; r++) {
      const float4 p1 = *reinterpret_cast<const float4*>(&sm.part[0][r0 + r][c4 * 4]);
      const float4 p2 = *reinterpret_cast<const float4*>(&sm.part[1][r0 + r][c4 * 4]);
      const float4 p3 = *reinterpret_cast<const float4*>(&sm.part[2][r0 + r][c4 * 4]);
      const float a0 = lo32(acc01[r]), a1 = hi32(acc01[r]);
      const float a2 = lo32(acc23[r]), a3 = hi32(acc23[r]);
      float v[4] = {((a0 + p1.x) + p2.x) + p3.x + bb.x,
                    ((a1 + p1.y) + p2.y) + p3.y + bb.y,
                    ((a2 + p1.z) + p2.z) + p3.z + bb.z,
                    ((a3 + p1.w) + p2.w) + p3.w + bb.w};
      #pragma unroll
      for (int j = 0; j < 4; j++) {
        if (ACT == 1) v[j] = v[j] > 0.f ? v[j] : 0.f;
        if (ACT == 2 || ACT == 3) v[j] = sigf(v[j]);
        if (ACT == 3) v[j] += 1e-8f;
      }
      const float4 o = make_float4(v[0], v[1], v[2], v[3]);
      if (outs) *reinterpret_cast<float4*>(&outs[r0 + r][c4 * 4]) = o;
      if (outg)
        reinterpret_cast<float4*>(outg)[(size_t)(grow0 + r0 + r) * NG + c4] = o;
    }
  }
  __syncthreads();
}

__global__ void __launch_bounds__(NTA, 1) acsq_ab(Params p)
{
  extern __shared__ char smraw[];
  SmemAB& sm = *reinterpret_cast<SmemAB*>(smraw);
  const int tid = threadIdx.x;

  if ((int)blockIdx.x < p.nClsBlk) {
    // ================= CLASS PATH: 16 classes =================
    const int c0 = blockIdx.x * RB;

    pf(sm.wbuf[0], p.W1, 128 * 128);
    {   // embed gather: 16 rows x 32 float4
      const int r = tid >> 5, col = tid & 31, cls = c0 + r;
      float4 v = make_float4(0.f, 0.f, 0.f, 0.f);
      if (cls < p.NC)
        v = __ldg(reinterpret_cast<const float4*>(p.embed + (size_t)cls * 128) + col);
      reinterpret_cast<float4*>(sm.A[r])[col] = v;
    }
    cpa_wait0(); __syncthreads();

    pf(sm.wbuf[1], p.W2, 128 * 128);
    layerW<128, 128, 1>(sm.A, sm.wbuf[0], p.b1, sm.Bb, nullptr, 0, sm);
    cpa_wait0(); __syncthreads();

    pf(sm.wbuf[0], p.W3, 128 * 128);
    layerW<128, 128, 1>(sm.Bb, sm.wbuf[1], p.b2, sm.A, nullptr, 0, sm);
    cpa_wait0(); __syncthreads();

    pf(sm.wbuf[1], p.Wp, 128 * 64);
    layerW<128, 128, 1>(sm.A, sm.wbuf[0], p.b3, sm.Bb, nullptr, 0, sm);
    cpa_wait0(); __syncthreads();

    layerW<128, 64, 0>(sm.Bb, sm.wbuf[1], p.bp, sm.A, nullptr, 0, sm);
    // z in A[:,0:64]
    if (tid < RB) {
      float s = 0.f;
      #pragma unroll
      for (int k = 0; k < 64; k++) s = fmaf(sm.A[tid][k], sm.A[tid][k], s);
      sm.znorm[tid] = s;
    }
    __syncthreads();

    // ---- VQ distances: one thread per code; FFMA2 paired across k ----
    {
      const int cc = tid;
      if (cc < p.VQN) {
        ulonglong2 cb[16];
        const ulonglong2* cp =
            reinterpret_cast<const ulonglong2*>(p.codebook + (size_t)cc * 64);
        #pragma unroll
        for (int q = 0; q < 16; q++) cb[q] = __ldg(cp + q);
        unsigned long long cn2 = 0ull;
        #pragma unroll
        for (int q = 0; q < 16; q++) { fma2(cn2, cb[q].x, cb[q].x); fma2(cn2, cb[q].y, cb[q].y); }
        const float cn = lo32(cn2) + hi32(cn2);
        #pragma unroll
        for (int r = 0; r < RB; r++) {
          const ulonglong2* A2 = reinterpret_cast<const ulonglong2*>(sm.A[r]);
          unsigned long long dot2 = 0ull;
          #pragma unroll
          for (int q = 0; q < 16; q++) {
            const ulonglong2 a = A2[q];           // broadcast LDS.128
            fma2(dot2, a.x, cb[q].x);
            fma2(dot2, a.y, cb[q].y);
          }
          const float dot = lo32(dot2) + hi32(dot2);
          sm.dist[r][cc] = sm.znorm[r] - 2.f * dot + cn;
        }
      }
    }
    __syncthreads();

    // ---- argmin per row (warp r of 16), lexicographic (d, idx) ----
    const int warp = tid >> 5, lane = tid & 31;
    {
      const int r = warp;
      float best = 3.4e38f; int bi = 0;
      for (int cc = lane; cc < p.VQN; cc += 32) {
        const float d = sm.dist[r][cc];
        if (d < best) { best = d; bi = cc; }
      }
      #pragma unroll
      for (int o = 16; o; o >>= 1) {
        const float ob = __shfl_down_sync(0xffffffffu, best, o);
        const int   oi = __shfl_down_sync(0xffffffffu, bi,   o);
        if (ob < best || (ob == best && oi < bi)) { best = ob; bi = oi; }
      }
      bi = __shfl_sync(0xffffffffu, bi, 0);
      float ls = 0.f;
      for (int k = lane; k < 64; k += 32) {
        const float dq = __ldg(p.codebook + (size_t)bi * 64 + k) - sm.A[r][k];
        ls = fmaf(dq, dq, ls);
      }
      #pragma unroll
      for (int o = 16; o; o >>= 1) ls += __shfl_down_sync(0xffffffffu, ls, o);
      if (lane == 0 && c0 + r < p.NC) {
        g_idx_cls[c0 + r]  = bi;
        g_loss_cls[c0 + r] = ls;
      }
    }
  } else {
    // ================= HEAD PATH: 16 codes =================
    const int q0 = (blockIdx.x - p.nClsBlk) * RB;

    pf(sm.wbuf[0], p.Wa, 64 * 128);
    if (tid < RB * 16) {     // gather 16 codebook rows
      const int r = tid >> 4, col = tid & 15;
      reinterpret_cast<float4*>(sm.A[r])[col] =
          __ldg(reinterpret_cast<const float4*>(p.codebook + (size_t)(q0 + r) * 64) + col);
    }
    cpa_wait0(); __syncthreads();

    pf(sm.wbuf[1], p.Ws, 64 * 128);
    layerW<64, 128, 2>(sm.A, sm.wbuf[0], p.ba, nullptr, g_tbl_actor, q0, sm);
    cpa_wait0(); __syncthreads();

    pf(sm.wbuf[0], p.Wc1, 64 * 128);
    layerW<64, 128, 3>(sm.A, sm.wbuf[1], p.bs, nullptr, g_tbl_scale, q0, sm);
    cpa_wait0(); __syncthreads();

    pf(sm.wbuf[1], p.Wc2, 128 * 128);
    layerW<64, 128, 2>(sm.A, sm.wbuf[0], p.bc1, sm.Bb, nullptr, 0, sm);
    cpa_wait0(); __syncthreads();

    pf(sm.wbuf[0], p.Wc3, 128 * 32);
    layerW<128, 128, 2>(sm.Bb, sm.wbuf[1], p.bc2, sm.A, nullptr, 0, sm);
    cpa_wait0(); __syncthreads();

    layerW<128, 32, 2>(sm.A, sm.wbuf[0], p.bc3, sm.Bb, nullptr, 0, sm);

    if (tid < RB) {
      float s = __ldg(p.bc4);
      #pragma unroll
      for (int k = 0; k < 32; k++) s = fmaf(sm.Bb[tid][k], __ldg(p.Wc4 + k), s);
      g_tbl_crit[q0 + tid] = s;
    }
  }
}

// ======= gather (R4 version, proven 26 us) + fused final loss reduce =======
__global__ void __launch_bounds__(NTG) acsq_gather(Params p, float scale)
{
  __shared__ int   codes[NTG];
  __shared__ float red[8];
  __shared__ float s[NTG];
  __shared__ bool  lastblk;
  const int tid = threadIdx.x;
  const size_t row0 = (size_t)blockIdx.x * NTG;
  const size_t b = row0 + tid;

  float lp = 0.f;
  int code = 0;
  if (b < (size_t)p.B) {
    const int o = p.obs[b];
    code = g_idx_cls[o];
    lp = g_loss_cls[o];
    p.out_idx[b]    = (float)code;
    p.out_critic[b] = g_tbl_crit[code];
  }
  codes[tid] = code;

  #pragma unroll
  for (int o = 16; o; o >>= 1) lp += __shfl_down_sync(0xffffffffu, lp, o);
  if ((tid & 31) == 0) red[tid >> 5] = lp;
  __syncthreads();
  if (tid == 0) {
    float t = 0.f;
    #pragma unroll
    for (int w = 0; w < 8; w++) t += red[w];
    g_partials[blockIdx.x] = t;
    __threadfence();
    lastblk = (atomicAdd(&g_ticket, 1u) == (unsigned)(gridDim.x - 1));
  }

  const float4* ta = reinterpret_cast<const float4*>(g_tbl_actor);
  const float4* ts = reinterpret_cast<const float4*>(g_tbl_scale);
  float4* oa = reinterpret_cast<float4*>(p.out_actor);
  float4* os = reinterpret_cast<float4*>(p.out_scale);
  __syncthreads();
  for (int i = tid; i < NTG * 32; i += NTG) {
    const int r = i >> 5, cc = i & 31;
    if (row0 + r < (size_t)p.B) {
      const int cd = codes[r];
      oa[(row0 + r) * 32 + cc] = ta[cd * 32 + cc];
      os[(row0 + r) * 32 + cc] = ts[cd * 32 + cc];
    }
  }

  if (lastblk) {
    float v = 0.f;
    for (int i = tid; i < p.gblocks; i += NTG) v += g_partials[i];  // fixed order
    s[tid] = v;
    __syncthreads();
    for (int o = NTG / 2; o > 0; o >>= 1) {
      if (tid < o) s[tid] += s[tid + o];
      __syncthreads();
    }
    if (tid == 0) { *p.out_loss = s[0] * scale; g_ticket = 0u; }
  }
}

extern "C" void kernel_launch(void* const* d_in, const int* in_sizes, int n_in,
                              void* d_out, int out_size)
{
  Params p;
  p.obs      = (const int*)d_in[0];
  p.embed    = (const float*)d_in[1];
  p.W1  = (const float*)d_in[2];  p.b1  = (const float*)d_in[3];
  p.W2  = (const float*)d_in[4];  p.b2  = (const float*)d_in[5];
  p.W3  = (const float*)d_in[6];  p.b3  = (const float*)d_in[7];
  p.Wp  = (const float*)d_in[8];  p.bp  = (const float*)d_in[9];
  p.codebook = (const float*)d_in[10];
  p.Wa  = (const float*)d_in[11]; p.ba  = (const float*)d_in[12];
  p.Ws  = (const float*)d_in[13]; p.bs  = (const float*)d_in[14];
  p.Wc1 = (const float*)d_in[15]; p.bc1 = (const float*)d_in[16];
  p.Wc2 = (const float*)d_in[17]; p.bc2 = (const float*)d_in[18];
  p.Wc3 = (const float*)d_in[19]; p.bc3 = (const float*)d_in[20];
  p.Wc4 = (const float*)d_in[21]; p.bc4 = (const float*)d_in[22];

  const int B   = in_sizes[0];
  const int NC  = in_sizes[1] / 128;   // embed is [NC, 128]
  const int VQN = in_sizes[10] / 64;   // codebook is [VQN, 64]
  p.B = B; p.NC = NC; p.VQN = VQN;
  p.nClsBlk = (NC + RB - 1) / RB;
  p.gblocks = (B + NTG - 1) / NTG;

  float* out = (float*)d_out;
  p.out_actor  = out;                                  // [B,128]
  p.out_scale  = out + (size_t)B * 128;                // [B,128]
  p.out_critic = out + (size_t)2 * B * 128;            // [B]
  p.out_loss   = out + (size_t)2 * B * 128 + B;        // scalar
  p.out_idx    = out + (size_t)2 * B * 128 + B + 1;    // [B] as float

  const int headBlk = (VQN + RB - 1) / RB;
  cudaFuncSetAttribute(acsq_ab, cudaFuncAttributeMaxDynamicSharedMemorySize,
                       (int)sizeof(SmemAB));
  acsq_ab<<<p.nClsBlk + headBlk, NTA, sizeof(SmemAB)>>>(p);
  acsq_gather<<<p.gblocks, NTG>>>(p, 1.25f / ((float)B * 64.f));
}

// round 10
// speedup vs baseline: 1.2870x; 1.0293x over previous
#include <cuda_runtime.h>
#include <math.h>

#define NTA 512    // ab kernel threads
#define NTG 256    // gather kernel threads
#define RB  16     // rows (classes/codes) per ab block

struct Params {
  const int*   obs;
  const float *embed, *W1, *b1, *W2, *b2, *W3, *b3, *Wp, *bp, *codebook;
  const float *Wa, *ba, *Ws, *bs, *Wc1, *bc1, *Wc2, *bc2, *Wc3, *bc3, *Wc4, *bc4;
  float *out_actor, *out_scale, *out_critic, *out_loss, *out_idx;
  int NC, VQN, nClsBlk, B, gblocks;
};

// Device-global scratch (no allocation allowed)
__device__ int      g_idx_cls[1024];
__device__ float    g_loss_cls[1024];
__device__ float    g_tbl_actor[512 * 128];
__device__ float    g_tbl_scale[512 * 128];
__device__ float    g_tbl_crit[512];
__device__ float    g_partials[1024];
__device__ unsigned g_ticket;

struct SmemAB {
  float wbuf[2][16384];     // 128 KB double-buffered weights
  float A[RB][128];         // 8 KB
  float Bb[RB][128];        // 8 KB
  float part[3][RB][128];   // 24 KB k-quarter partials
  float dist[RB][512];      // 32 KB
  float znorm[RB];
  alignas(8) unsigned long long mbar[2];
};                          // ~200 KB

__device__ __forceinline__ float sigf(float x) { return 1.0f / (1.0f + expf(-x)); }

// ---------------- packed f32x2 helpers ----------------
__device__ __forceinline__ unsigned long long pack_dup(float a) {
  unsigned long long d;
  const unsigned ai = __float_as_uint(a);
  asm("mov.b64 %0, {%1, %1};" : "=l"(d) : "r"(ai));
  return d;
}
__device__ __forceinline__ void fma2(unsigned long long& d, unsigned long long a,
                                     unsigned long long b) {
  asm("fma.rn.f32x2 %0, %1, %2, %0;" : "+l"(d) : "l"(a), "l"(b));
}
__device__ __forceinline__ float lo32(unsigned long long v) {
  return __uint_as_float((unsigned)(v & 0xffffffffull));
}
__device__ __forceinline__ float hi32(unsigned long long v) {
  return __uint_as_float((unsigned)(v >> 32));
}

// ---------------- bulk-copy + mbarrier helpers ----------------
__device__ __forceinline__ unsigned smaddr(const void* p) {
  return (unsigned)__cvta_generic_to_shared(p);
}
__device__ __forceinline__ void mbar_init(unsigned mbar, unsigned count) {
  asm volatile("mbarrier.init.shared.b64 [%0], %1;" :: "r"(mbar), "r"(count) : "memory");
}
// single-thread: announce tx bytes (this is also the single arrival) + launch bulk
__device__ __forceinline__ void bulk_stage(unsigned sdst, const void* gsrc,
                                           unsigned bytes, unsigned mbar) {
  asm volatile("mbarrier.arrive.expect_tx.shared.b64 _, [%0], %1;"
               :: "r"(mbar), "r"(bytes) : "memory");
  asm volatile("cp.async.bulk.shared::cta.global.mbarrier::complete_tx::bytes "
               "[%0], [%1], %2, [%3];"
               :: "r"(sdst), "l"(gsrc), "r"(bytes), "r"(mbar) : "memory");
}
__device__ __forceinline__ void mbar_wait(unsigned mbar, int phase) {
  asm volatile(
      "{\n\t"
      ".reg .pred P;\n\t"
      "WAIT_%=:\n\t"
      "mbarrier.try_wait.parity.acquire.cta.shared::cta.b64 P, [%0], %1, 0x989680;\n\t"
      "@P bra.uni DONE_%=;\n\t"
      "bra.uni WAIT_%=;\n\t"
      "DONE_%=:\n\t"
      "}"
      :: "r"(mbar), "r"(phase) : "memory");
}

__device__ __forceinline__ float comp4(const float4& v, int j) {
  return j == 0 ? v.x : j == 1 ? v.y : j == 2 ? v.z : v.w;
}

// ---- 16-row GEMM layer, (kq, colquarter) warp x (slot, rowgroup) lane ----
// FFMA2 paired across COLUMNS: each column's k-sum order unchanged.
// ACT: 0 linear, 1 relu, 2 sigmoid, 3 sigmoid+1e-8
template<int K, int N, int ACT>
__device__ __forceinline__ void layerW(const float (*__restrict__ in)[128],
                                       const float* __restrict__ wb,
                                       const float* __restrict__ bias_g,
                                       float (*__restrict__ outs)[128],
                                       float* __restrict__ outg, int grow0,
                                       SmemAB& sm)
{
  const int tid = threadIdx.x, warp = tid >> 5, lane = tid & 31;
  const int kq = warp >> 2, cq = warp & 3;
  constexpr int NG  = N / 4;      // float4 per output row
  constexpr int SPC = NG / 4;     // float4 slots per column-quarter
  const int slot = lane & 7, rg = lane >> 3;
  const int c4 = cq * SPC + slot; // this lane's float4 column
  const int r0 = rg * 4;          // this lane's 4 rows
  const bool active = slot < SPC;

  unsigned long long acc01[4], acc23[4];   // per row: col pairs (c0,c1),(c2,c3)
  #pragma unroll
  for (int r = 0; r < 4; r++) { acc01[r] = 0ull; acc23[r] = 0ull; }

  if (active) {
    const ulonglong2* w2 = reinterpret_cast<const ulonglong2*>(wb) + c4;
    const int kbeg = kq * (K / 4), kend = kbeg + (K / 4);
    #pragma unroll 2
    for (int k = kbeg; k < kend; k += 4) {
      float4 a[4];
      #pragma unroll
      for (int r = 0; r < 4; r++)
        a[r] = *reinterpret_cast<const float4*>(&in[r0 + r][k]);
      #pragma unroll
      for (int j = 0; j < 4; j++) {
        const ulonglong2 w = w2[(size_t)(k + j) * NG];
        #pragma unroll
        for (int r = 0; r < 4; r++) {
          const unsigned long long aa = pack_dup(comp4(a[r], j));
          fma2(acc01[r], aa, w.x);
          fma2(acc23[r], aa, w.y);
        }
      }
    }
  }
  if (kq > 0 && active) {
    #pragma unroll
    for (int r = 0; r < 4; r++) {
      const float4 o = make_float4(lo32(acc01[r]), hi32(acc01[r]),
                                   lo32(acc23[r]), hi32(acc23[r]));
      *reinterpret_cast<float4*>(&sm.part[kq - 1][r0 + r][c4 * 4]) = o;
    }
  }
  __syncthreads();
  if (kq == 0 && active) {
    const float4 bb = __ldg(reinterpret_cast<const float4*>(bias_g) + c4);
    #pragma unroll
    for (int r = 0; r < 4; r++) {
      const float4 p1 = *reinterpret_cast<const float4*>(&sm.part[0][r0 + r][c4 * 4]);
      const float4 p2 = *reinterpret_cast<const float4*>(&sm.part[1][r0 + r][c4 * 4]);
      const float4 p3 = *reinterpret_cast<const float4*>(&sm.part[2][r0 + r][c4 * 4]);
      const float a0 = lo32(acc01[r]), a1 = hi32(acc01[r]);
      const float a2 = lo32(acc23[r]), a3 = hi32(acc23[r]);
      float v[4] = {((a0 + p1.x) + p2.x) + p3.x + bb.x,
                    ((a1 + p1.y) + p2.y) + p3.y + bb.y,
                    ((a2 + p1.z) + p2.z) + p3.z + bb.z,
                    ((a3 + p1.w) + p2.w) + p3.w + bb.w};
      #pragma unroll
      for (int j = 0; j < 4; j++) {
        if (ACT == 1) v[j] = v[j] > 0.f ? v[j] : 0.f;
        if (ACT == 2 || ACT == 3) v[j] = sigf(v[j]);
        if (ACT == 3) v[j] += 1e-8f;
      }
      const float4 o = make_float4(v[0], v[1], v[2], v[3]);
      if (outs) *reinterpret_cast<float4*>(&outs[r0 + r][c4 * 4]) = o;
      if (outg)
        reinterpret_cast<float4*>(outg)[(size_t)(grow0 + r0 + r) * NG + c4] = o;
    }
  }
  __syncthreads();
}

__global__ void __launch_bounds__(NTA, 1) acsq_ab(Params p)
{
  extern __shared__ char smraw[];
  SmemAB& sm = *reinterpret_cast<SmemAB*>(smraw);
  const int tid = threadIdx.x;
  const unsigned mb0 = smaddr(&sm.mbar[0]), mb1 = smaddr(&sm.mbar[1]);
  const unsigned wb0 = smaddr(&sm.wbuf[0][0]), wb1 = smaddr(&sm.wbuf[1][0]);

  if (tid == 0) { mbar_init(mb0, 1); mbar_init(mb1, 1); }
  __syncthreads();

  if ((int)blockIdx.x < p.nClsBlk) {
    // ================= CLASS PATH: 16 classes =================
    const int c0 = blockIdx.x * RB;

    if (tid == 0) bulk_stage(wb0, p.W1, 128 * 128 * 4, mb0);
    {   // embed gather: 16 rows x 32 float4 (overlaps with bulk)
      const int r = tid >> 5, col = tid & 31, cls = c0 + r;
      float4 v = make_float4(0.f, 0.f, 0.f, 0.f);
      if (cls < p.NC)
        v = __ldg(reinterpret_cast<const float4*>(p.embed + (size_t)cls * 128) + col);
      reinterpret_cast<float4*>(sm.A[r])[col] = v;
    }
    if (tid == 0) bulk_stage(wb1, p.W2, 128 * 128 * 4, mb1);
    __syncthreads();                                   // A visible to all

    mbar_wait(mb0, 0);
    layerW<128, 128, 1>(sm.A, sm.wbuf[0], p.b1, sm.Bb, nullptr, 0, sm);
    if (tid == 0) bulk_stage(wb0, p.W3, 128 * 128 * 4, mb0);

    mbar_wait(mb1, 0);
    layerW<128, 128, 1>(sm.Bb, sm.wbuf[1], p.b2, sm.A, nullptr, 0, sm);
    if (tid == 0) bulk_stage(wb1, p.Wp, 128 * 64 * 4, mb1);

    mbar_wait(mb0, 1);
    layerW<128, 128, 1>(sm.A, sm.wbuf[0], p.b3, sm.Bb, nullptr, 0, sm);

    mbar_wait(mb1, 1);
    layerW<128, 64, 0>(sm.Bb, sm.wbuf[1], p.bp, sm.A, nullptr, 0, sm);
    // z in A[:,0:64]
    if (tid < RB) {
      float s = 0.f;
      #pragma unroll
      for (int k = 0; k < 64; k++) s = fmaf(sm.A[tid][k], sm.A[tid][k], s);
      sm.znorm[tid] = s;
    }
    __syncthreads();

    // ---- VQ distances: one thread per code; FFMA2 paired across k ----
    {
      const int cc = tid;
      if (cc < p.VQN) {
        ulonglong2 cb[16];
        const ulonglong2* cp =
            reinterpret_cast<const ulonglong2*>(p.codebook + (size_t)cc * 64);
        #pragma unroll
        for (int q = 0; q < 16; q++) cb[q] = __ldg(cp + q);
        unsigned long long cn2 = 0ull;
        #pragma unroll
        for (int q = 0; q < 16; q++) { fma2(cn2, cb[q].x, cb[q].x); fma2(cn2, cb[q].y, cb[q].y); }
        const float cn = lo32(cn2) + hi32(cn2);
        #pragma unroll
        for (int r = 0; r < RB; r++) {
          const ulonglong2* A2 = reinterpret_cast<const ulonglong2*>(sm.A[r]);
          unsigned long long dot2 = 0ull;
          #pragma unroll
          for (int q = 0; q < 16; q++) {
            const ulonglong2 a = A2[q];           // broadcast LDS.128
            fma2(dot2, a.x, cb[q].x);
            fma2(dot2, a.y, cb[q].y);
          }
          const float dot = lo32(dot2) + hi32(dot2);
          sm.dist[r][cc] = sm.znorm[r] - 2.f * dot + cn;
        }
      }
    }
    __syncthreads();

    // ---- argmin per row (warp r of 16), lexicographic (d, idx) ----
    const int warp = tid >> 5, lane = tid & 31;
    {
      const int r = warp;
      float best = 3.4e38f; int bi = 0;
      for (int cc = lane; cc < p.VQN; cc += 32) {
        const float d = sm.dist[r][cc];
        if (d < best) { best = d; bi = cc; }
      }
      #pragma unroll
      for (int o = 16; o; o >>= 1) {
        const float ob = __shfl_down_sync(0xffffffffu, best, o);
        const int   oi = __shfl_down_sync(0xffffffffu, bi,   o);
        if (ob < best || (ob == best && oi < bi)) { best = ob; bi = oi; }
      }
      bi = __shfl_sync(0xffffffffu, bi, 0);
      float ls = 0.f;
      for (int k = lane; k < 64; k += 32) {
        const float dq = __ldg(p.codebook + (size_t)bi * 64 + k) - sm.A[r][k];
        ls = fmaf(dq, dq, ls);
      }
      #pragma unroll
      for (int o = 16; o; o >>= 1) ls += __shfl_down_sync(0xffffffffu, ls, o);
      if (lane == 0 && c0 + r < p.NC) {
        g_idx_cls[c0 + r]  = bi;
        g_loss_cls[c0 + r] = ls;
      }
    }
  } else {
    // ================= HEAD PATH: 16 codes =================
    const int q0 = (blockIdx.x - p.nClsBlk) * RB;

    if (tid == 0) bulk_stage(wb0, p.Wa, 64 * 128 * 4, mb0);
    if (tid < RB * 16) {     // gather 16 codebook rows (overlaps with bulk)
      const int r = tid >> 4, col = tid & 15;
      reinterpret_cast<float4*>(sm.A[r])[col] =
          __ldg(reinterpret_cast<const float4*>(p.codebook + (size_t)(q0 + r) * 64) + col);
    }
    if (tid == 0) bulk_stage(wb1, p.Ws, 64 * 128 * 4, mb1);
    __syncthreads();                                   // A visible to all

    mbar_wait(mb0, 0);
    layerW<64, 128, 2>(sm.A, sm.wbuf[0], p.ba, nullptr, g_tbl_actor, q0, sm);
    if (tid == 0) bulk_stage(wb0, p.Wc1, 64 * 128 * 4, mb0);

    mbar_wait(mb1, 0);
    layerW<64, 128, 3>(sm.A, sm.wbuf[1], p.bs, nullptr, g_tbl_scale, q0, sm);
    if (tid == 0) bulk_stage(wb1, p.Wc2, 128 * 128 * 4, mb1);

    mbar_wait(mb0, 1);
    layerW<64, 128, 2>(sm.A, sm.wbuf[0], p.bc1, sm.Bb, nullptr, 0, sm);
    if (tid == 0) bulk_stage(wb0, p.Wc3, 128 * 32 * 4, mb0);

    mbar_wait(mb1, 1);
    layerW<128, 128, 2>(sm.Bb, sm.wbuf[1], p.bc2, sm.A, nullptr, 0, sm);

    mbar_wait(mb0, 0);   // mb0's third use -> phase wraps to 0
    layerW<128, 32, 2>(sm.A, sm.wbuf[0], p.bc3, sm.Bb, nullptr, 0, sm);

    if (tid < RB) {
      float s = __ldg(p.bc4);
      #pragma unroll
      for (int k = 0; k < 32; k++) s = fmaf(sm.Bb[tid][k], __ldg(p.Wc4 + k), s);
      g_tbl_crit[q0 + tid] = s;
    }
  }
}

// ======= gather (R4 version, proven 26 us) + fused final loss reduce =======
__global__ void __launch_bounds__(NTG) acsq_gather(Params p, float scale)
{
  __shared__ int   codes[NTG];
  __shared__ float red[8];
  __shared__ float s[NTG];
  __shared__ bool  lastblk;
  const int tid = threadIdx.x;
  const size_t row0 = (size_t)blockIdx.x * NTG;
  const size_t b = row0 + tid;

  float lp = 0.f;
  int code = 0;
  if (b < (size_t)p.B) {
    const int o = p.obs[b];
    code = g_idx_cls[o];
    lp = g_loss_cls[o];
    p.out_idx[b]    = (float)code;
    p.out_critic[b] = g_tbl_crit[code];
  }
  codes[tid] = code;

  #pragma unroll
  for (int o = 16; o; o >>= 1) lp += __shfl_down_sync(0xffffffffu, lp, o);
  if ((tid & 31) == 0) red[tid >> 5] = lp;
  __syncthreads();
  if (tid == 0) {
    float t = 0.f;
    #pragma unroll
    for (int w = 0; w < 8; w++) t += red[w];
    g_partials[blockIdx.x] = t;
    __threadfence();
    lastblk = (atomicAdd(&g_ticket, 1u) == (unsigned)(gridDim.x - 1));
  }

  const float4* ta = reinterpret_cast<const float4*>(g_tbl_actor);
  const float4* ts = reinterpret_cast<const float4*>(g_tbl_scale);
  float4* oa = reinterpret_cast<float4*>(p.out_actor);
  float4* os = reinterpret_cast<float4*>(p.out_scale);
  __syncthreads();
  for (int i = tid; i < NTG * 32; i += NTG) {
    const int r = i >> 5, cc = i & 31;
    if (row0 + r < (size_t)p.B) {
      const int cd = codes[r];
      oa[(row0 + r) * 32 + cc] = ta[cd * 32 + cc];
      os[(row0 + r) * 32 + cc] = ts[cd * 32 + cc];
    }
  }

  if (lastblk) {
    float v = 0.f;
    for (int i = tid; i < p.gblocks; i += NTG) v += g_partials[i];  // fixed order
    s[tid] = v;
    __syncthreads();
    for (int o = NTG / 2; o > 0; o >>= 1) {
      if (tid < o) s[tid] += s[tid + o];
      __syncthreads();
    }
    if (tid == 0) { *p.out_loss = s[0] * scale; g_ticket = 0u; }
  }
}

extern "C" void kernel_launch(void* const* d_in, const int* in_sizes, int n_in,
                              void* d_out, int out_size)
{
  Params p;
  p.obs      = (const int*)d_in[0];
  p.embed    = (const float*)d_in[1];
  p.W1  = (const float*)d_in[2];  p.b1  = (const float*)d_in[3];
  p.W2  = (const float*)d_in[4];  p.b2  = (const float*)d_in[5];
  p.W3  = (const float*)d_in[6];  p.b3  = (const float*)d_in[7];
  p.Wp  = (const float*)d_in[8];  p.bp  = (const float*)d_in[9];
  p.codebook = (const float*)d_in[10];
  p.Wa  = (const float*)d_in[11]; p.ba  = (const float*)d_in[12];
  p.Ws  = (const float*)d_in[13]; p.bs  = (const float*)d_in[14];
  p.Wc1 = (const float*)d_in[15]; p.bc1 = (const float*)d_in[16];
  p.Wc2 = (const float*)d_in[17]; p.bc2 = (const float*)d_in[18];
  p.Wc3 = (const float*)d_in[19]; p.bc3 = (const float*)d_in[20];
  p.Wc4 = (const float*)d_in[21]; p.bc4 = (const float*)d_in[22];

  const int B   = in_sizes[0];
  const int NC  = in_sizes[1] / 128;   // embed is [NC, 128]
  const int VQN = in_sizes[10] / 64;   // codebook is [VQN, 64]
  p.B = B; p.NC = NC; p.VQN = VQN;
  p.nClsBlk = (NC + RB - 1) / RB;
  p.gblocks = (B + NTG - 1) / NTG;

  float* out = (float*)d_out;
  p.out_actor  = out;                                  // [B,128]
  p.out_scale  = out + (size_t)B * 128;                // [B,128]
  p.out_critic = out + (size_t)2 * B * 128;            // [B]
  p.out_loss   = out + (size_t)2 * B * 128 + B;        // scalar
  p.out_idx    = out + (size_t)2 * B * 128 + B + 1;    // [B] as float

  const int headBlk = (VQN + RB - 1) / RB;
  cudaFuncSetAttribute(acsq_ab, cudaFuncAttributeMaxDynamicSharedMemorySize,
                       (int)sizeof(SmemAB));
  acsq_ab<<<p.nClsBlk + headBlk, NTA, sizeof(SmemAB)>>>(p);
  acsq_gather<<<p.gblocks, NTG>>>(p, 1.25f / ((float)B * 64.f));
}

// round 11
// speedup vs baseline: 1.3282x; 1.0320x over previous
#include <cuda_runtime.h>
#include <math.h>

#define NTA 512    // ab kernel threads
#define NTG 256    // gather kernel threads
#define RB  16     // rows (classes/codes) per ab block
#define AP  132    // smem activation pitch (floats): 4-row stride != 0 mod 32 banks

struct Params {
  const int*   obs;
  const float *embed, *W1, *b1, *W2, *b2, *W3, *b3, *Wp, *bp, *codebook;
  const float *Wa, *ba, *Ws, *bs, *Wc1, *bc1, *Wc2, *bc2, *Wc3, *bc3, *Wc4, *bc4;
  float *out_actor, *out_scale, *out_critic, *out_loss, *out_idx;
  int NC, VQN, nClsBlk, B, gblocks;
};

// Device-global scratch (no allocation allowed)
__device__ int      g_idx_cls[1024];
__device__ float    g_loss_cls[1024];
__device__ float    g_tbl_actor[512 * 128];
__device__ float    g_tbl_scale[512 * 128];
__device__ float    g_tbl_crit[512];
__device__ float    g_partials[1024];
__device__ unsigned g_ticket;

struct SmemAB {
  float A[RB][AP];          // 8.4 KB
  float Bb[RB][AP];         // 8.4 KB
  float part[3][RB][AP];    // 25.3 KB k-quarter partials
  float dist[RB][512];      // 32 KB
  float znorm[RB];
};                          // ~75 KB

__device__ __forceinline__ float sigf(float x) { return 1.0f / (1.0f + expf(-x)); }

// ---------------- packed f32x2 helpers ----------------
__device__ __forceinline__ unsigned long long pack_dup(float a) {
  unsigned long long d;
  const unsigned ai = __float_as_uint(a);
  asm("mov.b64 %0, {%1, %1};" : "=l"(d) : "r"(ai));
  return d;
}
__device__ __forceinline__ void fma2(unsigned long long& d, unsigned long long a,
                                     unsigned long long b) {
  asm("fma.rn.f32x2 %0, %1, %2, %0;" : "+l"(d) : "l"(a), "l"(b));
}
__device__ __forceinline__ float lo32(unsigned long long v) {
  return __uint_as_float((unsigned)(v & 0xffffffffull));
}
__device__ __forceinline__ float hi32(unsigned long long v) {
  return __uint_as_float((unsigned)(v >> 32));
}

__device__ __forceinline__ float comp4(const float4& v, int j) {
  return j == 0 ? v.x : j == 1 ? v.y : j == 2 ? v.z : v.w;
}

// ---- 16-row GEMM layer; weights streamed DIRECTLY from global (L2-hot) ----
// warp w (16): kq = w>>2 (k-quarter), cq = w&3 (column quarter).
// lane: slot = lane&7 (float4 col in quarter), rg = lane>>3 (rows 4rg..4rg+3).
// Each weight element is consumed by exactly one thread -> no staging value.
// FFMA2 paired across columns: per-column k-sum order unchanged (bit-exact).
// ACT: 0 linear, 1 relu, 2 sigmoid, 3 sigmoid+1e-8
template<int K, int N, int ACT>
__device__ __forceinline__ void layerW(const float (*__restrict__ in)[AP],
                                       const float* __restrict__ wg,
                                       const float* __restrict__ bias_g,
                                       float (*__restrict__ outs)[AP],
                                       float* __restrict__ outg, int grow0,
                                       SmemAB& sm)
{
  const int tid = threadIdx.x, warp = tid >> 5, lane = tid & 31;
  const int kq = warp >> 2, cq = warp & 3;
  constexpr int NG  = N / 4;      // float4 per output row
  constexpr int SPC = NG / 4;     // float4 slots per column-quarter
  const int slot = lane & 7, rg = lane >> 3;
  const int c4 = cq * SPC + slot; // this lane's float4 column
  const int r0 = rg * 4;          // this lane's 4 rows
  const bool active = slot < SPC;

  unsigned long long acc01[4], acc23[4];   // per row: col pairs (c0,c1),(c2,c3)
  #pragma unroll
  for (int r = 0; r < 4; r++) { acc01[r] = 0ull; acc23[r] = 0ull; }

  if (active) {
    const ulonglong2* w2 = reinterpret_cast<const ulonglong2*>(wg) + c4;
    const int kbeg = kq * (K / 4), kend = kbeg + (K / 4);
    #pragma unroll 2
    for (int k = kbeg; k < kend; k += 4) {
      float4 a[4];
      #pragma unroll
      for (int r = 0; r < 4; r++)
        a[r] = *reinterpret_cast<const float4*>(&in[r0 + r][k]);
      ulonglong2 w[4];
      #pragma unroll
      for (int j = 0; j < 4; j++) w[j] = __ldg(&w2[(size_t)(k + j) * NG]);
      #pragma unroll
      for (int j = 0; j < 4; j++) {
        #pragma unroll
        for (int r = 0; r < 4; r++) {
          const unsigned long long aa = pack_dup(comp4(a[r], j));
          fma2(acc01[r], aa, w[j].x);
          fma2(acc23[r], aa, w[j].y);
        }
      }
    }
  }
  if (kq > 0 && active) {
    #pragma unroll
    for (int r = 0; r < 4; r++) {
      const float4 o = make_float4(lo32(acc01[r]), hi32(acc01[r]),
                                   lo32(acc23[r]), hi32(acc23[r]));
      *reinterpret_cast<float4*>(&sm.part[kq - 1][r0 + r][c4 * 4]) = o;
    }
  }
  __syncthreads();
  if (kq == 0 && active) {
    const float4 bb = __ldg(reinterpret_cast<const float4*>(bias_g) + c4);
    #pragma unroll
    for (int r = 0; r < 4; r++) {
      const float4 p1 = *reinterpret_cast<const float4*>(&sm.part[0][r0 + r][c4 * 4]);
      const float4 p2 = *reinterpret_cast<const float4*>(&sm.part[1][r0 + r][c4 * 4]);
      const float4 p3 = *reinterpret_cast<const float4*>(&sm.part[2][r0 + r][c4 * 4]);
      const float a0 = lo32(acc01[r]), a1 = hi32(acc01[r]);
      const float a2 = lo32(acc23[r]), a3 = hi32(acc23[r]);
      float v[4] = {((a0 + p1.x) + p2.x) + p3.x + bb.x,
                    ((a1 + p1.y) + p2.y) + p3.y + bb.y,
                    ((a2 + p1.z) + p2.z) + p3.z + bb.z,
                    ((a3 + p1.w) + p2.w) + p3.w + bb.w};
      #pragma unroll
      for (int j = 0; j < 4; j++) {
        if (ACT == 1) v[j] = v[j] > 0.f ? v[j] : 0.f;
        if (ACT == 2 || ACT == 3) v[j] = sigf(v[j]);
        if (ACT == 3) v[j] += 1e-8f;
      }
      const float4 o = make_float4(v[0], v[1], v[2], v[3]);
      if (outs) *reinterpret_cast<float4*>(&outs[r0 + r][c4 * 4]) = o;
      if (outg)
        reinterpret_cast<float4*>(outg)[(size_t)(grow0 + r0 + r) * NG + c4] = o;
    }
  }
  __syncthreads();
}

__global__ void __launch_bounds__(NTA, 1) acsq_ab(Params p)
{
  extern __shared__ char smraw[];
  SmemAB& sm = *reinterpret_cast<SmemAB*>(smraw);
  const int tid = threadIdx.x;

  if ((int)blockIdx.x < p.nClsBlk) {
    // ================= CLASS PATH: 16 classes =================
    const int c0 = blockIdx.x * RB;

    {   // embed gather: 16 rows x 32 float4
      const int r = tid >> 5, col = tid & 31, cls = c0 + r;
      float4 v = make_float4(0.f, 0.f, 0.f, 0.f);
      if (cls < p.NC)
        v = __ldg(reinterpret_cast<const float4*>(p.embed + (size_t)cls * 128) + col);
      reinterpret_cast<float4*>(sm.A[r])[col] = v;
    }
    __syncthreads();

    layerW<128, 128, 1>(sm.A,  p.W1, p.b1, sm.Bb, nullptr, 0, sm);
    layerW<128, 128, 1>(sm.Bb, p.W2, p.b2, sm.A,  nullptr, 0, sm);
    layerW<128, 128, 1>(sm.A,  p.W3, p.b3, sm.Bb, nullptr, 0, sm);
    layerW<128, 64, 0>(sm.Bb,  p.Wp, p.bp, sm.A,  nullptr, 0, sm);
    // z in A[:,0:64]
    if (tid < RB) {
      float s = 0.f;
      #pragma unroll
      for (int k = 0; k < 64; k++) s = fmaf(sm.A[tid][k], sm.A[tid][k], s);
      sm.znorm[tid] = s;
    }
    __syncthreads();

    // ---- VQ distances: one thread per code; FFMA2 paired across k ----
    {
      const int cc = tid;
      if (cc < p.VQN) {
        ulonglong2 cb[16];
        const ulonglong2* cp =
            reinterpret_cast<const ulonglong2*>(p.codebook + (size_t)cc * 64);
        #pragma unroll
        for (int q = 0; q < 16; q++) cb[q] = __ldg(cp + q);
        unsigned long long cn2 = 0ull;
        #pragma unroll
        for (int q = 0; q < 16; q++) { fma2(cn2, cb[q].x, cb[q].x); fma2(cn2, cb[q].y, cb[q].y); }
        const float cn = lo32(cn2) + hi32(cn2);
        #pragma unroll
        for (int r = 0; r < RB; r++) {
          const ulonglong2* A2 = reinterpret_cast<const ulonglong2*>(sm.A[r]);
          unsigned long long dot2 = 0ull;
          #pragma unroll
          for (int q = 0; q < 16; q++) {
            const ulonglong2 a = A2[q];           // broadcast LDS.128
            fma2(dot2, a.x, cb[q].x);
            fma2(dot2, a.y, cb[q].y);
          }
          const float dot = lo32(dot2) + hi32(dot2);
          sm.dist[r][cc] = sm.znorm[r] - 2.f * dot + cn;
        }
      }
    }
    __syncthreads();

    // ---- argmin per row (warp r of 16), lexicographic (d, idx) ----
    const int warp = tid >> 5, lane = tid & 31;
    {
      const int r = warp;
      float best = 3.4e38f; int bi = 0;
      for (int cc = lane; cc < p.VQN; cc += 32) {
        const float d = sm.dist[r][cc];
        if (d < best) { best = d; bi = cc; }
      }
      #pragma unroll
      for (int o = 16; o; o >>= 1) {
        const float ob = __shfl_down_sync(0xffffffffu, best, o);
        const int   oi = __shfl_down_sync(0xffffffffu, bi,   o);
        if (ob < best || (ob == best && oi < bi)) { best = ob; bi = oi; }
      }
      bi = __shfl_sync(0xffffffffu, bi, 0);
      float ls = 0.f;
      for (int k = lane; k < 64; k += 32) {
        const float dq = __ldg(p.codebook + (size_t)bi * 64 + k) - sm.A[r][k];
        ls = fmaf(dq, dq, ls);
      }
      #pragma unroll
      for (int o = 16; o; o >>= 1) ls += __shfl_down_sync(0xffffffffu, ls, o);
      if (lane == 0 && c0 + r < p.NC) {
        g_idx_cls[c0 + r]  = bi;
        g_loss_cls[c0 + r] = ls;
      }
    }
  } else {
    // ================= HEAD PATH: 16 codes =================
    const int q0 = (blockIdx.x - p.nClsBlk) * RB;

    if (tid < RB * 16) {     // gather 16 codebook rows
      const int r = tid >> 4, col = tid & 15;
      reinterpret_cast<float4*>(sm.A[r])[col] =
          __ldg(reinterpret_cast<const float4*>(p.codebook + (size_t)(q0 + r) * 64) + col);
    }
    __syncthreads();

    layerW<64, 128, 2>(sm.A,  p.Wa,  p.ba,  nullptr, g_tbl_actor, q0, sm);
    layerW<64, 128, 3>(sm.A,  p.Ws,  p.bs,  nullptr, g_tbl_scale, q0, sm);
    layerW<64, 128, 2>(sm.A,  p.Wc1, p.bc1, sm.Bb,   nullptr, 0, sm);
    layerW<128, 128, 2>(sm.Bb, p.Wc2, p.bc2, sm.A,   nullptr, 0, sm);
    layerW<128, 32, 2>(sm.A,  p.Wc3, p.bc3, sm.Bb,   nullptr, 0, sm);

    if (tid < RB) {
      float s = __ldg(p.bc4);
      #pragma unroll
      for (int k = 0; k < 32; k++) s = fmaf(sm.Bb[tid][k], __ldg(p.Wc4 + k), s);
      g_tbl_crit[q0 + tid] = s;
    }
  }
}

// ======= gather (R4 version, proven 26 us) + fused final loss reduce =======
__global__ void __launch_bounds__(NTG) acsq_gather(Params p, float scale)
{
  __shared__ int   codes[NTG];
  __shared__ float red[8];
  __shared__ float s[NTG];
  __shared__ bool  lastblk;
  const int tid = threadIdx.x;
  const size_t row0 = (size_t)blockIdx.x * NTG;
  const size_t b = row0 + tid;

  float lp = 0.f;
  int code = 0;
  if (b < (size_t)p.B) {
    const int o = p.obs[b];
    code = g_idx_cls[o];
    lp = g_loss_cls[o];
    p.out_idx[b]    = (float)code;
    p.out_critic[b] = g_tbl_crit[code];
  }
  codes[tid] = code;

  #pragma unroll
  for (int o = 16; o; o >>= 1) lp += __shfl_down_sync(0xffffffffu, lp, o);
  if ((tid & 31) == 0) red[tid >> 5] = lp;
  __syncthreads();
  if (tid == 0) {
    float t = 0.f;
    #pragma unroll
    for (int w = 0; w < 8; w++) t += red[w];
    g_partials[blockIdx.x] = t;
    __threadfence();
    lastblk = (atomicAdd(&g_ticket, 1u) == (unsigned)(gridDim.x - 1));
  }

  const float4* ta = reinterpret_cast<const float4*>(g_tbl_actor);
  const float4* ts = reinterpret_cast<const float4*>(g_tbl_scale);
  float4* oa = reinterpret_cast<float4*>(p.out_actor);
  float4* os = reinterpret_cast<float4*>(p.out_scale);
  __syncthreads();
  for (int i = tid; i < NTG * 32; i += NTG) {
    const int r = i >> 5, cc = i & 31;
    if (row0 + r < (size_t)p.B) {
      const int cd = codes[r];
      oa[(row0 + r) * 32 + cc] = ta[cd * 32 + cc];
      os[(row0 + r) * 32 + cc] = ts[cd * 32 + cc];
    }
  }

  if (lastblk) {
    float v = 0.f;
    for (int i = tid; i < p.gblocks; i += NTG) v += g_partials[i];  // fixed order
    s[tid] = v;
    __syncthreads();
    for (int o = NTG / 2; o > 0; o >>= 1) {
      if (tid < o) s[tid] += s[tid + o];
      __syncthreads();
    }
    if (tid == 0) { *p.out_loss = s[0] * scale; g_ticket = 0u; }
  }
}

extern "C" void kernel_launch(void* const* d_in, const int* in_sizes, int n_in,
                              void* d_out, int out_size)
{
  Params p;
  p.obs      = (const int*)d_in[0];
  p.embed    = (const float*)d_in[1];
  p.W1  = (const float*)d_in[2];  p.b1  = (const float*)d_in[3];
  p.W2  = (const float*)d_in[4];  p.b2  = (const float*)d_in[5];
  p.W3  = (const float*)d_in[6];  p.b3  = (const float*)d_in[7];
  p.Wp  = (const float*)d_in[8];  p.bp  = (const float*)d_in[9];
  p.codebook = (const float*)d_in[10];
  p.Wa  = (const float*)d_in[11]; p.ba  = (const float*)d_in[12];
  p.Ws  = (const float*)d_in[13]; p.bs  = (const float*)d_in[14];
  p.Wc1 = (const float*)d_in[15]; p.bc1 = (const float*)d_in[16];
  p.Wc2 = (const float*)d_in[17]; p.bc2 = (const float*)d_in[18];
  p.Wc3 = (const float*)d_in[19]; p.bc3 = (const float*)d_in[20];
  p.Wc4 = (const float*)d_in[21]; p.bc4 = (const float*)d_in[22];

  const int B   = in_sizes[0];
  const int NC  = in_sizes[1] / 128;   // embed is [NC, 128]
  const int VQN = in_sizes[10] / 64;   // codebook is [VQN, 64]
  p.B = B; p.NC = NC; p.VQN = VQN;
  p.nClsBlk = (NC + RB - 1) / RB;
  p.gblocks = (B + NTG - 1) / NTG;

  float* out = (float*)d_out;
  p.out_actor  = out;                                  // [B,128]
  p.out_scale  = out + (size_t)B * 128;                // [B,128]
  p.out_critic = out + (size_t)2 * B * 128;            // [B]
  p.out_loss   = out + (size_t)2 * B * 128 + B;        // scalar
  p.out_idx    = out + (size_t)2 * B * 128 + B + 1;    // [B] as float

  const int headBlk = (VQN + RB - 1) / RB;
  cudaFuncSetAttribute(acsq_ab, cudaFuncAttributeMaxDynamicSharedMemorySize,
                       (int)sizeof(SmemAB));
  acsq_ab<<<p.nClsBlk + headBlk, NTA, sizeof(SmemAB)>>>(p);
  acsq_gather<<<p.gblocks, NTG>>>(p, 1.25f / ((float)B * 64.f));
}